// round 8
// baseline (speedup 1.0000x reference)
#include <cuda_runtime.h>
#include <math.h>

#define BB 8
#define XX 128
#define YY 128
#define WW 24
#define DD 4
#define YHH 65
#define NPIX (BB*XX*YY)        // 131072
#define NROWS (BB*XX)          // 1024
#define NFREQ (XX*YHH)         // 8320
#define IOSZ (WW*WW)           // 576

// ---------------- device scratch (static: no allocations allowed) ------------
__device__ float  d_h[(size_t)NPIX*WW];             // (B,X,Y,W)      12.6 MB
__device__ float2 d_hf[(size_t)NROWS*YHH*WW];       // (B,X,YH,W)     12.8 MB
__device__ float2 d_spec[(size_t)NROWS*YHH*WW];     // (B,X,YH,W)     12.8 MB
__device__ float2 d_wt[(size_t)DD*NFREQ*IOSZ];      // (D,f,i,o)     153.4 MB
__device__ float2 d_tw[128];                        // exp(-i*pi*k/64)

__device__ __forceinline__ float4 cmul4(float4 v, float2 w) {
    return make_float4(v.x*w.x - v.y*w.y, v.x*w.y + v.y*w.x,
                       v.z*w.x - v.w*w.y, v.z*w.y + v.w*w.x);
}
__device__ __forceinline__ float4 add4(float4 a, float4 b) {
    return make_float4(a.x+b.x, a.y+b.y, a.z+b.z, a.w+b.w);
}
__device__ __forceinline__ float4 sub4(float4 a, float4 b) {
    return make_float4(a.x-b.x, a.y-b.y, a.z-b.z, a.w-b.w);
}
// fwd: multiply both packed complex by -j ; inv: by +j
template<bool INV>
__device__ __forceinline__ float4 mulj4(float4 v) {
    return INV ? make_float4(-v.y, v.x, -v.w, v.z)
               : make_float4( v.y,-v.x,  v.w,-v.z);
}

// ---------------- twiddle table ----------------------------------------------
__global__ void k_twiddle() {
    int k = threadIdx.x;
    double s, c;
    sincospi(-(double)k / 64.0, &s, &c);
    d_tw[k] = make_float2((float)c, (float)s);
}

// ---------------- weight transpose: (d, io, f) -> (d, f, io) ------------------
__global__ void k_transpose(const float2* __restrict__ src) {
    __shared__ float2 tile[32][33];
    int dd  = blockIdx.z;
    int f0  = blockIdx.x * 32;
    int io0 = blockIdx.y * 32;
    const float2* s = src + (size_t)dd * IOSZ * NFREQ;
    #pragma unroll
    for (int j = 0; j < 4; j++) {
        int io = io0 + threadIdx.y + j*8;
        int f  = f0 + threadIdx.x;
        tile[threadIdx.y + j*8][threadIdx.x] = s[(size_t)io * NFREQ + f];
    }
    __syncthreads();
    float2* dst = d_wt + (size_t)dd * NFREQ * IOSZ;
    #pragma unroll
    for (int j = 0; j < 4; j++) {
        int f  = f0 + threadIdx.y + j*8;
        int io = io0 + threadIdx.x;
        dst[(size_t)f * IOSZ + io] = tile[threadIdx.x][threadIdx.y + j*8];
    }
}

// ---------------- 128-point Stockham FFT, radix 4*4*8, fused I/O --------------
// LP float4 lanes per point (2 complex lines each). Layout buf[point*LP + lp].
// Stage 1 reads via ld(point, lp); stage 3 writes via st(point, lp, val).
// s1: ld -> b0; sync; s2: b0 -> b1; sync; s3: b1 -> st. NO trailing sync.
template<int LP, bool INV, int NT, class LD, class ST>
__device__ __forceinline__ void fft128_io(float4* b0, float4* b1, int tid,
                                          const float2* __restrict__ tw,
                                          LD ld, ST st) {
    // -------- stage 1: radix-4, s=1 --------
    #pragma unroll 2
    for (int idx = tid; idx < 32*LP; idx += NT) {
        int lp = idx % LP;
        int p  = idx / LP;                     // 0..31
        float4 a = ld(p,      lp);
        float4 b = ld(p + 32, lp);
        float4 c = ld(p + 64, lp);
        float4 d = ld(p + 96, lp);
        float2 w1 = tw[p], w2 = tw[2*p], w3 = tw[3*p];
        if (INV) { w1.y = -w1.y; w2.y = -w2.y; w3.y = -w3.y; }
        float4 apc = add4(a, c), amc = sub4(a, c);
        float4 bpd = add4(b, d), bmd = sub4(b, d);
        float4 jb  = mulj4<INV>(bmd);
        int ob = 4*p;
        b0[(ob    )*LP + lp] = add4(apc, bpd);
        b0[(ob + 1)*LP + lp] = cmul4(add4(amc, jb), w1);
        b0[(ob + 2)*LP + lp] = cmul4(sub4(apc, bpd), w2);
        b0[(ob + 3)*LP + lp] = cmul4(sub4(amc, jb), w3);
    }
    __syncthreads();
    // -------- stage 2: radix-4, s=4 --------
    #pragma unroll 2
    for (int idx = tid; idx < 32*LP; idx += NT) {
        int lp = idx % LP;
        int bf = idx / LP;
        int q = bf & 3, p = bf >> 2;           // p 0..7
        int base = q + 4*p;
        float4 a = b0[ base      *LP + lp];
        float4 b = b0[(base+32 )*LP + lp];
        float4 c = b0[(base+64 )*LP + lp];
        float4 d = b0[(base+96 )*LP + lp];
        float2 w1 = tw[4*p], w2 = tw[8*p], w3 = tw[12*p];
        if (INV) { w1.y = -w1.y; w2.y = -w2.y; w3.y = -w3.y; }
        float4 apc = add4(a, c), amc = sub4(a, c);
        float4 bpd = add4(b, d), bmd = sub4(b, d);
        float4 jb  = mulj4<INV>(bmd);
        int ob = q + 16*p;
        b1[(ob     )*LP + lp] = add4(apc, bpd);
        b1[(ob + 4 )*LP + lp] = cmul4(add4(amc, jb), w1);
        b1[(ob + 8 )*LP + lp] = cmul4(sub4(apc, bpd), w2);
        b1[(ob + 12)*LP + lp] = cmul4(sub4(amc, jb), w3);
    }
    __syncthreads();
    // -------- stage 3: radix-8, s=16, p=0 (no table twiddles) --------
    const float C = 0.70710678118654752f;
    #pragma unroll 2
    for (int idx = tid; idx < 16*LP; idx += NT) {
        int lp = idx % LP;
        int q  = idx / LP;                     // 0..15
        float4 x0 = b1[(q       )*LP + lp];
        float4 x1 = b1[(q + 16 )*LP + lp];
        float4 x2 = b1[(q + 32 )*LP + lp];
        float4 x3 = b1[(q + 48 )*LP + lp];
        float4 x4 = b1[(q + 64 )*LP + lp];
        float4 x5 = b1[(q + 80 )*LP + lp];
        float4 x6 = b1[(q + 96 )*LP + lp];
        float4 x7 = b1[(q + 112)*LP + lp];
        float4 t0 = add4(x0, x4), t1 = sub4(x0, x4);
        float4 t2 = add4(x2, x6), t3 = sub4(x2, x6);
        float4 jt3 = mulj4<INV>(t3);
        float4 e0 = add4(t0, t2), e2 = sub4(t0, t2);
        float4 e1 = add4(t1, jt3), e3 = sub4(t1, jt3);
        float4 u0 = add4(x1, x5), u1 = sub4(x1, x5);
        float4 u2 = add4(x3, x7), u3 = sub4(x3, x7);
        float4 ju3 = mulj4<INV>(u3);
        float4 o0 = add4(u0, u2), o2 = sub4(u0, u2);
        float4 o1 = add4(u1, ju3), o3 = sub4(u1, ju3);
        float2 w81 = INV ? make_float2( C,  C) : make_float2( C, -C);
        float2 w83 = INV ? make_float2(-C,  C) : make_float2(-C, -C);
        float4 o1w = cmul4(o1, w81);
        float4 o2w = mulj4<INV>(o2);
        float4 o3w = cmul4(o3, w83);
        st(q      , lp, add4(e0, o0));
        st(q + 16 , lp, add4(e1, o1w));
        st(q + 32 , lp, add4(e2, o2w));
        st(q + 48 , lp, add4(e3, o3w));
        st(q + 64 , lp, sub4(e0, o0));
        st(q + 80 , lp, sub4(e1, o1w));
        st(q + 96 , lp, sub4(e2, o2w));
        st(q + 112, lp, sub4(e3, o3w));
    }
}

// ---------------- in mapping ---------------------------------------------------
__global__ void k_inmap(const float* __restrict__ x,
                        const float* __restrict__ iw,
                        const float* __restrict__ ib) {
    int p = blockIdx.x * blockDim.x + threadIdx.x;
    if (p >= NPIX) return;
    float a = x[2*p], b = x[2*p + 1];
    float* out = d_h + (size_t)p * WW;
    #pragma unroll
    for (int w = 0; w < WW; w++)
        out[w] = a*iw[w] + b*iw[WW + w] + ib[w];
}

// ---------------- rfft along y per (b,x) row (runs once) ----------------------
__global__ void k_rfft_y() {
    extern __shared__ float4 sm4[];
    float4* bufA = sm4;                 // 128*12
    float4* bufB = sm4 + 128*12;
    __shared__ float2 tw[128];
    int tid = threadIdx.x;
    if (tid < 128) tw[tid] = d_tw[tid];
    __syncthreads();
    int row = blockIdx.x;
    const float* hsrc = d_h + (size_t)row * YY * WW;
    float4* hfo = (float4*)(d_hf + (size_t)row * YHH * WW);
    auto ld = [&](int p, int lp) {
        return make_float4(hsrc[p*24 + 2*lp], 0.0f, hsrc[p*24 + 2*lp + 1], 0.0f);
    };
    auto st = [&](int p, int lp, float4 v) {
        if (p < YHH) hfo[p*12 + lp] = v;
    };
    fft128_io<12,false,512>(bufA, bufB, tid, tw, ld, st);
}

// ---------------- fused fft-x + spectral matmul + ifft-x ----------------------
// block = (yh, batch-pair of 2). 48 lines = 24 float4 lanes. smem 96KB, 2 CTA/SM
__global__ __launch_bounds__(512) void k_spectral(int layer) {
    extern __shared__ float4 sm4[];
    float4* bufA = sm4;                 // 128*24
    float4* bufB = sm4 + 128*24;
    __shared__ float2 tw[128];
    int tid = threadIdx.x;
    if (tid < 128) tw[tid] = d_tw[tid];
    __syncthreads();
    int yh  = blockIdx.x >> 2;
    int b0i = (blockIdx.x & 3) * 2;

    // forward x-FFT: gather from d_hf in stage 1, result F -> bufA
    const float4* hf4 = (const float4*)d_hf;
    auto ldf = [&](int p, int lp) {
        int b = b0i + lp/12, ip = lp % 12;
        return hf4[(((size_t)b*XX + p)*YHH + yh)*12 + ip];
    };
    auto stf = [&](int p, int lp, float4 v) { bufA[p*24 + lp] = v; };
    fft128_io<24,false,512>(bufA, bufB, tid, tw, ldf, stf);
    __syncthreads();

    // yf[b][o] = sum_i hf[b][i] * w[i][o]; 2 batches x 2 outputs per thread-j
    const float2* wt = d_wt + (size_t)layer * NFREQ * IOSZ;
    const float2* F = (const float2*)bufA;
    float4* G4 = bufB;
    #pragma unroll 2
    for (int j = tid; j < 128*12; j += 512) {
        int x = j / 12, op = j % 12, o = op * 2;
        const float4* wp4 = (const float4*)(wt + ((size_t)x*YHH + yh)*IOSZ + o);
        const float2* hp  = F + x*48;
        float2 a00 = {0,0}, a01 = {0,0}, a10 = {0,0}, a11 = {0,0};
        #pragma unroll
        for (int i = 0; i < WW; i++) {
            float4 w4 = __ldg(wp4 + i*12);           // w[i][o], w[i][o+1]
            float2 w0 = make_float2(w4.x, w4.y);
            float2 w1 = make_float2(w4.z, w4.w);
            float2 h0 = hp[i], h1 = hp[24+i];
            a00.x += h0.x*w0.x - h0.y*w0.y;  a00.y += h0.x*w0.y + h0.y*w0.x;
            a01.x += h0.x*w1.x - h0.y*w1.y;  a01.y += h0.x*w1.y + h0.y*w1.x;
            a10.x += h1.x*w0.x - h1.y*w0.y;  a10.y += h1.x*w0.y + h1.y*w0.x;
            a11.x += h1.x*w1.x - h1.y*w1.y;  a11.y += h1.x*w1.y + h1.y*w1.x;
        }
        G4[(x*48 + o) >> 1]      = make_float4(a00.x, a00.y, a01.x, a01.y);
        G4[(x*48 + 24 + o) >> 1] = make_float4(a10.x, a10.y, a11.x, a11.y);
    }
    __syncthreads();

    // inverse x-FFT: stage 1 reads G (bufB), stage 3 scatters to d_spec
    float4* sp4 = (float4*)d_spec;
    auto ldi = [&](int p, int lp) { return bufB[p*24 + lp]; };
    auto sti = [&](int p, int lp, float4 v) {
        int b = b0i + lp/12, ip = lp % 12;
        sp4[(((size_t)b*XX + p)*YHH + yh)*12 + ip] = v;
    };
    fft128_io<24,true,512>(bufA, bufB, tid, tw, ldi, sti);
}

// ---------------- fused irfft-y + 1x1 conv + relu (+ out-map) (+ next rfft-y) -
// 2 rows per block, 256 threads. Channel-pair packing: 12 complex lines per row
// carry 24 real channels. Hermitian pack (with DC/Nyquist imag drop) is fused
// into the inverse FFT's stage-1 global gather.
__global__ __launch_bounds__(256) void k_update(int layer, int t, int Trt, int flags,
                         const float* __restrict__ conv_w,
                         const float* __restrict__ conv_b,
                         const float* __restrict__ out_w,
                         const float* __restrict__ out_b,
                         float* __restrict__ outp) {
    extern __shared__ float4 sm4[];
    float4* A4  = sm4;                        // 128*12 (2 rows x 6 lanes)
    float4* B4  = sm4 + 128*12;
    float*  hrow = (float*)(sm4 + 2*128*12);  // 2*128*24 floats
    __shared__ float2 tw[128];
    int tid = threadIdx.x;
    if (tid < 128) tw[tid] = d_tw[tid];
    int row0 = blockIdx.x * 2;

    // load previous h (2 contiguous rows) for the 1x1 conv
    {
        const float4* hsrc4 = (const float4*)(d_h + (size_t)row0 * YY * WW);
        float4* hrow4 = (float4*)hrow;
        for (int i = tid; i < 2*YY*WW/4; i += 256) hrow4[i] = hsrc4[i];
    }
    __syncthreads();   // tw visible; hrow ordered by later barriers

    // inverse y-FFT with fused Hermitian pack; result R -> A4
    const float4* spec4 = (const float4*)(d_spec + (size_t)row0 * YHH * WW);
    auto ldp = [&](int k, int lp) {
        int r = lp / 6, cp = lp % 6;
        const float4* sp = spec4 + (size_t)r * YHH * 12;
        float2 z0, z1;
        if (k == 0 || k == 64) {
            float4 v0 = sp[k*12 + 2*cp], v1 = sp[k*12 + 2*cp + 1];
            z0 = make_float2(v0.x, v0.z);
            z1 = make_float2(v1.x, v1.z);
        } else if (k < 64) {
            float4 v0 = sp[k*12 + 2*cp], v1 = sp[k*12 + 2*cp + 1];
            z0 = make_float2(v0.x - v0.w, v0.y + v0.z);
            z1 = make_float2(v1.x - v1.w, v1.y + v1.z);
        } else {
            float4 v0 = sp[(128-k)*12 + 2*cp], v1 = sp[(128-k)*12 + 2*cp + 1];
            z0 = make_float2(v0.x + v0.w, v0.z - v0.y);
            z1 = make_float2(v1.x + v1.w, v1.z - v1.y);
        }
        return make_float4(z0.x, z0.y, z1.x, z1.y);
    };
    auto stR = [&](int p, int lp, float4 v) { A4[p*12 + lp] = v; };
    fft128_io<12,true,256>(A4, B4, tid, tw, ldp, stR);
    __syncthreads();

    // conv + relu; packed h_new pairs -> B4 (P) and global d_h
    const float* cw = conv_w + layer * IOSZ;
    const float* cb = conv_b + layer * WW;
    const float2* R2 = (const float2*)A4;     // [y*24 + r*12 + c]
    float2* P2 = (float2*)B4;
    #pragma unroll 2
    for (int idx = tid; idx < 2*128*12; idx += 256) {
        int y = idx / 24, l = idx % 24;
        int r = l / 12, c = l % 12, o = 2*c;
        float2 z = R2[idx];
        float acc0 = cb[o], acc1 = cb[o+1];
        const float* hr = hrow + r*YY*WW + y*WW;
        #pragma unroll
        for (int i = 0; i < WW; i++) {
            float hv = hr[i];
            float2 w = __ldg((const float2*)(cw + i*WW + o));
            acc0 += hv * w.x;
            acc1 += hv * w.y;
        }
        float hn0 = fmaxf(z.x * (1.0f/16384.0f), 0.0f) + acc0;
        float hn1 = fmaxf(z.y * (1.0f/16384.0f), 0.0f) + acc1;
        P2[idx] = make_float2(hn0, hn1);
        ((float2*)(d_h + (size_t)(row0 + r) * YY * WW))[y*12 + c] =
            make_float2(hn0, hn1);
    }
    __syncthreads();

    if (flags & 1) {   // out mapping (COUT = 1); reads P before fwd FFT clobbers
        int r = tid >> 7, y = tid & 127;
        int row = row0 + r;
        int b = row >> 7, xs = row & 127;
        float s = out_b[0];
        #pragma unroll
        for (int c = 0; c < 12; c++) {
            float2 z = P2[y*24 + r*12 + c];
            s += z.x * __ldg(out_w + 2*c) + z.y * __ldg(out_w + 2*c + 1);
        }
        outp[(((size_t)b*Trt + t)*XX + xs)*YY + y] = s;
    }

    if (flags & 2) {   // forward rfft-y of packed h_new, then unscramble
        auto ldP = [&](int p, int lp) { return B4[p*12 + lp]; };
        auto stZ = [&](int p, int lp, float4 v) { A4[p*12 + lp] = v; };
        fft128_io<12,false,256>(A4, B4, tid, tw, ldP, stZ);
        __syncthreads();
        const float2* Z2 = (const float2*)A4;
        float4* hfo = (float4*)(d_hf + (size_t)row0 * YHH * WW);
        #pragma unroll 2
        for (int idx = tid; idx < YHH*24; idx += 256) {
            int k = idx / 24, l = idx % 24;
            int r = l / 12, c = l % 12;
            float2 Zk = Z2[k*24 + l];
            float2 Zm = Z2[((128 - k) & 127)*24 + l];
            // A = (Z[k] + conj(Z[-k]))/2 ; B = (Z[k] - conj(Z[-k]))/(2i)
            float ax = 0.5f*(Zk.x + Zm.x), ay = 0.5f*(Zk.y - Zm.y);
            float bx = 0.5f*(Zk.y + Zm.y), by = 0.5f*(Zm.x - Zk.x);
            hfo[((size_t)r*YHH + k)*12 + c] = make_float4(ax, ay, bx, by);
        }
    }
}

// ---------------- host launcher ----------------------------------------------
extern "C" void kernel_launch(void* const* d_in, const int* in_sizes, int n_in,
                              void* d_out, int out_size) {
    const float* x      = (const float*)d_in[0];
    const float* in_w   = (const float*)d_in[1];
    const float* in_b   = (const float*)d_in[2];
    const float* spec_w = (const float*)d_in[3];
    const float* conv_w = (const float*)d_in[4];
    const float* conv_b = (const float*)d_in[5];
    const float* out_w  = (const float*)d_in[6];
    const float* out_b  = (const float*)d_in[7];
    float* outp = (float*)d_out;
    int Trt = out_size / (BB * XX * YY);

    const int SMEM_ROW  = 2 * 128 * 12 * (int)sizeof(float4);     // 49152
    const int SMEM_SPEC = 2 * 128 * 24 * (int)sizeof(float4);     // 98304
    const int SMEM_UPD  = 2 * 128 * 12 * (int)sizeof(float4)
                        + 2 * 128 * WW * (int)sizeof(float);      // 73728
    cudaFuncSetAttribute(k_spectral, cudaFuncAttributeMaxDynamicSharedMemorySize, SMEM_SPEC);
    cudaFuncSetAttribute(k_rfft_y,   cudaFuncAttributeMaxDynamicSharedMemorySize, SMEM_ROW);
    cudaFuncSetAttribute(k_update,   cudaFuncAttributeMaxDynamicSharedMemorySize, SMEM_UPD);

    k_twiddle<<<1, 128>>>();

    dim3 tb(32, 8), tg(NFREQ/32, IOSZ/32, DD);
    k_transpose<<<tg, tb>>>((const float2*)spec_w);

    k_inmap<<<(NPIX + 255)/256, 256>>>(x, in_w, in_b);
    k_rfft_y<<<NROWS, 512, SMEM_ROW>>>();

    for (int t = 0; t < Trt; t++) {
        for (int d = 0; d < DD; d++) {
            k_spectral<<<4*YHH, 512, SMEM_SPEC>>>(d);
            int flags = (d == DD-1 ? 1 : 0)
                      | ((t == Trt-1 && d == DD-1) ? 0 : 2);
            k_update<<<NROWS/2, 256, SMEM_UPD>>>(d, t, Trt, flags,
                                                 conv_w, conv_b, out_w, out_b, outp);
        }
    }
}